// round 2
// baseline (speedup 1.0000x reference)
#include <cuda_runtime.h>
#include <math.h>

// Problem constants (fixed by dataset)
#define MAXN 100000
#define MAXE 1600000
#define NEG_SLOPE 0.2f

// ---------------- scratch (static __device__, no allocs) ----------------
__device__ float g_h[(size_t)MAXN * 128];     // 51.2 MB: h = elu(x)@W, [N,128]
__device__ float g_asrc[MAXN * 2];            // per-node attention halves
__device__ float g_adst[MAXN * 2];
__device__ int   g_deg[MAXN];
__device__ int   g_starts[MAXN + 1];
__device__ int   g_cursor[MAXN];
__device__ int   g_ssrc[MAXE + MAXN];         // src index sorted by dst (incl self loops)

// ---------------- helpers ----------------
__device__ __forceinline__ float elu_f(float v)   { return v > 0.f ? v : expm1f(v); }
__device__ __forceinline__ float lrelu_f(float v) { return v > 0.f ? v : NEG_SLOPE * v; }

__device__ __forceinline__ unsigned long long pack2(float a, float b) {
    unsigned long long r;
    asm("mov.b64 %0, {%1,%2};" : "=l"(r) : "f"(a), "f"(b));
    return r;
}
__device__ __forceinline__ void unpack2(unsigned long long v, float &a, float &b) {
    asm("mov.b64 {%0,%1}, %2;" : "=f"(a), "=f"(b) : "l"(v));
}
// Packed dual-FMA: 2 fp32 FMAs per instruction (PTX-only on Blackwell)
__device__ __forceinline__ void fma2(unsigned long long &c, unsigned long long a, unsigned long long b) {
    asm("fma.rn.f32x2 %0, %1, %2, %0;" : "+l"(c) : "l"(a), "l"(b));
}

// ---------------- K0: init degrees (1 = self loop) + cursors ----------------
__global__ void k_init(int n) {
    int i = blockIdx.x * blockDim.x + threadIdx.x;
    if (i < n) { g_deg[i] = 1; g_cursor[i] = 0; }
}

// ---------------- K1: histogram of dst (edge_index is int32!) ----------------
__global__ void k_hist(const int* __restrict__ ei, int e) {
    int i = blockIdx.x * blockDim.x + threadIdx.x;
    if (i < e) {
        int d = ei[e + i];
        atomicAdd(&g_deg[d], 1);
    }
}

// ---------------- K2: single-block exclusive scan over deg -> starts ----------------
__global__ void k_scan(int n) {
    __shared__ int part[1024];
    int tid = threadIdx.x;
    int chunk = (n + 1023) >> 10;
    int base = tid * chunk;
    int s = 0;
    for (int i = 0; i < chunk; i++) {
        int id = base + i;
        if (id < n) s += g_deg[id];
    }
    part[tid] = s;
    __syncthreads();
    // Hillis-Steele inclusive scan
    for (int off = 1; off < 1024; off <<= 1) {
        int v = (tid >= off) ? part[tid - off] : 0;
        __syncthreads();
        part[tid] += v;
        __syncthreads();
    }
    int run = tid ? part[tid - 1] : 0;
    for (int i = 0; i < chunk; i++) {
        int id = base + i;
        if (id < n) { g_starts[id] = run; run += g_deg[id]; }
    }
    if (tid == 1023) g_starts[n] = part[1023];
}

// ---------------- K3: scatter edges into dst-sorted order; self loop at segment end ----------------
__global__ void k_scatter(const int* __restrict__ ei, int e, int n) {
    int i = blockIdx.x * blockDim.x + threadIdx.x;
    if (i < e) {
        int s = ei[i];
        int d = ei[e + i];
        int p = g_starts[d] + atomicAdd(&g_cursor[d], 1);
        g_ssrc[p] = s;
    } else if (i < e + n) {
        int nn = i - e;                     // self loop (nn -> nn)
        g_ssrc[g_starts[nn + 1] - 1] = nn;  // slot deg-1 is reserved for it
    }
}

// ---------------- K4: h = elu(x) @ W   (128x128 weight, fma.f32x2) ----------------
// Block: 128 threads, 32 nodes/block. Thread = (og in 0..15, ng in 0..7).
// Thread computes 4 nodes (ng*4..+3) x 8 outs: pairs {og*2+j*32, og*2+j*32+1}, j=0..3.
__global__ __launch_bounds__(128) void k_gemm(const float* __restrict__ x,
                                              const float* __restrict__ W, int n) {
    __shared__ float sW[64 * 128];   // K-tile 64 x 128 outs (32 KB)
    __shared__ float sX[32 * 68];    // 32 nodes x 64 k (stride 68 to dodge bank conflicts)
    int tid = threadIdx.x;
    int og = tid & 15, ng = tid >> 4;
    int nodeBase = blockIdx.x * 32;

    unsigned long long acc[4][4];
    #pragma unroll
    for (int a = 0; a < 4; a++)
        #pragma unroll
        for (int j = 0; j < 4; j++) acc[a][j] = 0ull;   // bits of {0.f,0.f}

    for (int kk = 0; kk < 128; kk += 64) {
        // load W tile (contiguous rows kk..kk+63)
        #pragma unroll
        for (int i = 0; i < 16; i++) {
            int idx = i * 128 + tid;     // 2048 float4 total
            ((float4*)sW)[idx] = ((const float4*)(W + kk * 128))[idx];
        }
        // load X tile with ELU
        #pragma unroll
        for (int i = 0; i < 4; i++) {
            int idx = i * 128 + tid;     // 512 float4 total
            int node = idx >> 4;
            int col = idx & 15;
            int gn = nodeBase + node;
            float4 v = make_float4(0.f, 0.f, 0.f, 0.f);
            if (gn < n) v = ((const float4*)(x + (size_t)gn * 128 + kk))[col];
            v.x = elu_f(v.x); v.y = elu_f(v.y); v.z = elu_f(v.z); v.w = elu_f(v.w);
            ((float4*)(sX + node * 68))[col] = v;
        }
        __syncthreads();

        #pragma unroll 8
        for (int k = 0; k < 64; k++) {
            unsigned long long wv[4];
            #pragma unroll
            for (int j = 0; j < 4; j++)
                wv[j] = *(const unsigned long long*)&sW[k * 128 + og * 2 + j * 32];
            #pragma unroll
            for (int a = 0; a < 4; a++) {
                float xv = sX[(ng * 4 + a) * 68 + k];
                unsigned long long xp = pack2(xv, xv);
                #pragma unroll
                for (int j = 0; j < 4; j++) fma2(acc[a][j], xp, wv[j]);
            }
        }
        __syncthreads();
    }

    #pragma unroll
    for (int a = 0; a < 4; a++) {
        int gn = nodeBase + ng * 4 + a;
        if (gn < n) {
            #pragma unroll
            for (int j = 0; j < 4; j++) {
                float lo, hi;
                unpack2(acc[a][j], lo, hi);
                *(float2*)&g_h[(size_t)gn * 128 + og * 2 + j * 32] = make_float2(lo, hi);
            }
        }
    }
}

// ---------------- K5: per-node attention halves a_src/a_dst ----------------
// One warp per (node, head): dot(h[n,h,:], att_*) over 64 dims.
__global__ __launch_bounds__(256) void k_att(const float* __restrict__ att_src,
                                             const float* __restrict__ att_dst, int n) {
    int gw = (blockIdx.x * blockDim.x + threadIdx.x) >> 5;
    int lane = threadIdx.x & 31;
    int node = gw >> 1, head = gw & 1;
    if (node >= n) return;
    const float* hr = &g_h[(size_t)node * 128 + head * 64];
    float v0 = hr[lane], v1 = hr[lane + 32];
    float s = v0 * att_src[head * 64 + lane] + v1 * att_src[head * 64 + lane + 32];
    float d = v0 * att_dst[head * 64 + lane] + v1 * att_dst[head * 64 + lane + 32];
    #pragma unroll
    for (int o = 16; o; o >>= 1) {
        s += __shfl_xor_sync(0xffffffffu, s, o);
        d += __shfl_xor_sync(0xffffffffu, d, o);
    }
    if (lane == 0) {
        g_asrc[node * 2 + head] = s;
        g_adst[node * 2 + head] = d;
    }
}

// ---------------- K6: per-dst warp — online segment softmax + weighted aggregation ----------------
__global__ __launch_bounds__(256) void k_agg(const float* __restrict__ bias,
                                             float* __restrict__ out, int n) {
    int warp = (blockIdx.x * blockDim.x + threadIdx.x) >> 5;
    int lane = threadIdx.x & 31;
    if (warp >= n) return;
    int node = warp;
    int beg = g_starts[node], end = g_starts[node + 1];

    float ad0 = g_adst[node * 2 + 0], ad1 = g_adst[node * 2 + 1];

    // Pass 1: online max + rescaled sum (lane-parallel over edges)
    float m0 = -INFINITY, m1 = -INFINITY, d0 = 0.f, d1 = 0.f;
    for (int i = beg + lane; i < end; i += 32) {
        int s = g_ssrc[i];
        float2 as = *(const float2*)&g_asrc[s * 2];
        float l0 = lrelu_f(as.x + ad0);
        float l1 = lrelu_f(as.y + ad1);
        float nm0 = fmaxf(m0, l0);
        d0 = d0 * __expf(m0 - nm0) + __expf(l0 - nm0); m0 = nm0;
        float nm1 = fmaxf(m1, l1);
        d1 = d1 * __expf(m1 - nm1) + __expf(l1 - nm1); m1 = nm1;
    }
    // warp combine ((m,d) pairs) — guarded against -inf/-inf NaN
    #pragma unroll
    for (int o = 16; o; o >>= 1) {
        float om0 = __shfl_xor_sync(0xffffffffu, m0, o);
        float od0 = __shfl_xor_sync(0xffffffffu, d0, o);
        float nm = fmaxf(m0, om0);
        float sa = (m0  > -INFINITY) ? __expf(m0 - nm)  : 0.f;
        float sb = (om0 > -INFINITY) ? __expf(om0 - nm) : 0.f;
        d0 = d0 * sa + od0 * sb; m0 = nm;

        float om1 = __shfl_xor_sync(0xffffffffu, m1, o);
        float od1 = __shfl_xor_sync(0xffffffffu, d1, o);
        float nm1b = fmaxf(m1, om1);
        float sc = (m1  > -INFINITY) ? __expf(m1 - nm1b)  : 0.f;
        float sd = (om1 > -INFINITY) ? __expf(om1 - nm1b) : 0.f;
        d1 = d1 * sc + od1 * sd; m1 = nm1b;
    }
    float inv0 = 1.f / (d0 + 1e-16f);
    float inv1 = 1.f / (d1 + 1e-16f);

    // Pass 2: accumulate alpha * h[src]; lane holds channels c..c+3 (c = lane*4,
    // which lands in head 0 for lanes 0..15 and head 1 for lanes 16..31)
    int head = lane >> 4;
    int c = lane * 4;
    float m   = head ? m1   : m0;
    float inv = head ? inv1 : inv0;
    float ad  = head ? ad1  : ad0;

    float4 acc = make_float4(0.f, 0.f, 0.f, 0.f);
    for (int i = beg; i < end; i++) {
        int s = g_ssrc[i];                       // uniform across warp
        float as = g_asrc[s * 2 + head];
        float l = lrelu_f(as + ad);
        float a = __expf(l - m) * inv;
        float4 hv = *(const float4*)&g_h[(size_t)s * 128 + c];
        acc.x = fmaf(a, hv.x, acc.x);
        acc.y = fmaf(a, hv.y, acc.y);
        acc.z = fmaf(a, hv.z, acc.z);
        acc.w = fmaf(a, hv.w, acc.w);
    }
    float4 bv = *(const float4*)&bias[c];
    *(float4*)&out[(size_t)node * 128 + c] =
        make_float4(acc.x + bv.x, acc.y + bv.y, acc.z + bv.z, acc.w + bv.w);
}

// ---------------- launch ----------------
extern "C" void kernel_launch(void* const* d_in, const int* in_sizes, int n_in,
                              void* d_out, int out_size) {
    const float* x       = (const float*)d_in[0];
    const int*   ei      = (const int*)d_in[1];    // int32 (JAX downcasts int64)
    const float* W       = (const float*)d_in[2];
    const float* att_src = (const float*)d_in[3];
    const float* att_dst = (const float*)d_in[4];
    const float* bias    = (const float*)d_in[5];
    float*       out     = (float*)d_out;

    int n = in_sizes[0] / 128;   // 100000
    int e = in_sizes[1] / 2;     // 1600000

    k_init<<<(n + 255) / 256, 256>>>(n);
    k_hist<<<(e + 255) / 256, 256>>>(ei, e);
    k_scan<<<1, 1024>>>(n);
    k_scatter<<<(e + n + 255) / 256, 256>>>(ei, e, n);

    k_gemm<<<(n + 31) / 32, 128>>>(x, W, n);
    k_att<<<(n * 2 + 7) / 8, 256>>>(att_src, att_dst, n);

    k_agg<<<(n + 7) / 8, 256>>>(bias, out, n);
}

// round 3
// speedup vs baseline: 1.0345x; 1.0345x over previous
#include <cuda_runtime.h>
#include <cuda_fp16.h>
#include <math.h>

// Problem constants (fixed by dataset)
#define MAXN 100000
#define MAXE 1600000
#define NEG_SLOPE 0.2f

// ---------------- scratch (static __device__, no allocs) ----------------
__device__ __half g_h[(size_t)MAXN * 128];    // 25.6 MB: h = elu(x)@W, [N,128] fp16
__device__ float g_asrc[MAXN * 2];            // per-node attention halves (fp32, from fp32 acc)
__device__ float g_adst[MAXN * 2];
__device__ int   g_deg[MAXN];
__device__ int   g_starts[MAXN + 1];
__device__ int   g_cursor[MAXN];
__device__ int   g_ssrc[MAXE + MAXN];         // src index sorted by dst (incl self loops)

// ---------------- helpers ----------------
__device__ __forceinline__ float elu_f(float v)   { return v > 0.f ? v : expm1f(v); }
__device__ __forceinline__ float lrelu_f(float v) { return v > 0.f ? v : NEG_SLOPE * v; }

__device__ __forceinline__ unsigned long long pack2(float a, float b) {
    unsigned long long r;
    asm("mov.b64 %0, {%1,%2};" : "=l"(r) : "f"(a), "f"(b));
    return r;
}
__device__ __forceinline__ void unpack2(unsigned long long v, float &a, float &b) {
    asm("mov.b64 {%0,%1}, %2;" : "=f"(a), "=f"(b) : "l"(v));
}
// Packed dual-FMA: 2 fp32 FMAs per instruction (PTX-only on Blackwell)
__device__ __forceinline__ void fma2(unsigned long long &c, unsigned long long a, unsigned long long b) {
    asm("fma.rn.f32x2 %0, %1, %2, %0;" : "+l"(c) : "l"(a), "l"(b));
}

// ---------------- K0: init degrees (1 = self loop) + cursors ----------------
__global__ void k_init(int n) {
    int i = blockIdx.x * blockDim.x + threadIdx.x;
    if (i < n) { g_deg[i] = 1; g_cursor[i] = 0; }
}

// ---------------- K1: histogram of dst (edge_index is int32) ----------------
__global__ void k_hist(const int* __restrict__ ei, int e) {
    int i = blockIdx.x * blockDim.x + threadIdx.x;
    if (i < e) {
        int d = ei[e + i];
        atomicAdd(&g_deg[d], 1);
    }
}

// ---------------- K2: single-block exclusive scan over deg -> starts ----------------
__global__ void k_scan(int n) {
    __shared__ int part[1024];
    int tid = threadIdx.x;
    int chunk = (n + 1023) >> 10;
    int base = tid * chunk;
    int s = 0;
    for (int i = 0; i < chunk; i++) {
        int id = base + i;
        if (id < n) s += g_deg[id];
    }
    part[tid] = s;
    __syncthreads();
    for (int off = 1; off < 1024; off <<= 1) {
        int v = (tid >= off) ? part[tid - off] : 0;
        __syncthreads();
        part[tid] += v;
        __syncthreads();
    }
    int run = tid ? part[tid - 1] : 0;
    for (int i = 0; i < chunk; i++) {
        int id = base + i;
        if (id < n) { g_starts[id] = run; run += g_deg[id]; }
    }
    if (tid == 1023) g_starts[n] = part[1023];
}

// ---------------- K3: scatter edges into dst-sorted order; self loop at segment end ----------------
__global__ void k_scatter(const int* __restrict__ ei, int e, int n) {
    int i = blockIdx.x * blockDim.x + threadIdx.x;
    if (i < e) {
        int s = ei[i];
        int d = ei[e + i];
        int p = g_starts[d] + atomicAdd(&g_cursor[d], 1);
        g_ssrc[p] = s;
    } else if (i < e + n) {
        int nn = i - e;                     // self loop (nn -> nn)
        g_ssrc[g_starts[nn + 1] - 1] = nn;  // slot deg-1 is reserved for it
    }
}

// ---------------- K4: h = elu(x) @ W  + fused a_src/a_dst epilogue ----------------
// Block: 128 threads, 32 nodes/block. Thread = (og in 0..15, ng in 0..7).
// Thread computes 4 nodes (ng*4..+3) x 8 outs: pairs {og*2+j*32, og*2+j*32+1}, j=0..3.
// j=0,1 -> head 0 channels; j=2,3 -> head 1 channels.
__global__ __launch_bounds__(128) void k_gemm(const float* __restrict__ x,
                                              const float* __restrict__ W,
                                              const float* __restrict__ att_src,
                                              const float* __restrict__ att_dst, int n) {
    __shared__ float sW[64 * 128];   // K-tile 64 x 128 outs (32 KB)
    __shared__ float sX[32 * 68];    // 32 nodes x 64 k (stride 68 to dodge bank conflicts)
    int tid = threadIdx.x;
    int og = tid & 15, ng = tid >> 4;
    int nodeBase = blockIdx.x * 32;

    unsigned long long acc[4][4];
    #pragma unroll
    for (int a = 0; a < 4; a++)
        #pragma unroll
        for (int j = 0; j < 4; j++) acc[a][j] = 0ull;

    for (int kk = 0; kk < 128; kk += 64) {
        #pragma unroll
        for (int i = 0; i < 16; i++) {
            int idx = i * 128 + tid;
            ((float4*)sW)[idx] = ((const float4*)(W + kk * 128))[idx];
        }
        #pragma unroll
        for (int i = 0; i < 4; i++) {
            int idx = i * 128 + tid;
            int node = idx >> 4;
            int col = idx & 15;
            int gn = nodeBase + node;
            float4 v = make_float4(0.f, 0.f, 0.f, 0.f);
            if (gn < n) v = ((const float4*)(x + (size_t)gn * 128 + kk))[col];
            v.x = elu_f(v.x); v.y = elu_f(v.y); v.z = elu_f(v.z); v.w = elu_f(v.w);
            ((float4*)(sX + node * 68))[col] = v;
        }
        __syncthreads();

        #pragma unroll 8
        for (int k = 0; k < 64; k++) {
            unsigned long long wv[4];
            #pragma unroll
            for (int j = 0; j < 4; j++)
                wv[j] = *(const unsigned long long*)&sW[k * 128 + og * 2 + j * 32];
            #pragma unroll
            for (int a = 0; a < 4; a++) {
                float xv = sX[(ng * 4 + a) * 68 + k];
                unsigned long long xp = pack2(xv, xv);
                #pragma unroll
                for (int j = 0; j < 4; j++) fma2(acc[a][j], xp, wv[j]);
            }
        }
        __syncthreads();
    }

    // att vector entries for this thread's 8 channels
    float as_v[4][2], ad_v[4][2];
    #pragma unroll
    for (int j = 0; j < 4; j++) {
        int head = j >> 1;
        int ch = og * 2 + (j & 1) * 32;             // channel within head
        as_v[j][0] = att_src[head * 64 + ch];
        as_v[j][1] = att_src[head * 64 + ch + 1];
        ad_v[j][0] = att_dst[head * 64 + ch];
        ad_v[j][1] = att_dst[head * 64 + ch + 1];
    }

    float ps[4][2], pd[4][2];                       // [node a][head]
    #pragma unroll
    for (int a = 0; a < 4; a++) { ps[a][0]=ps[a][1]=pd[a][0]=pd[a][1]=0.f; }

    #pragma unroll
    for (int a = 0; a < 4; a++) {
        int gn = nodeBase + ng * 4 + a;
        #pragma unroll
        for (int j = 0; j < 4; j++) {
            float lo, hi;
            unpack2(acc[a][j], lo, hi);
            int head = j >> 1;
            ps[a][head] += lo * as_v[j][0] + hi * as_v[j][1];
            pd[a][head] += lo * ad_v[j][0] + hi * ad_v[j][1];
            if (gn < n) {
                __half2 hv = __floats2half2_rn(lo, hi);
                *(__half2*)&g_h[(size_t)gn * 128 + og * 2 + j * 32] = hv;
            }
        }
    }

    // reduce partials over the 16 og-lanes (contiguous within warp half)
    #pragma unroll
    for (int off = 1; off < 16; off <<= 1) {
        #pragma unroll
        for (int a = 0; a < 4; a++) {
            ps[a][0] += __shfl_xor_sync(0xffffffffu, ps[a][0], off);
            ps[a][1] += __shfl_xor_sync(0xffffffffu, ps[a][1], off);
            pd[a][0] += __shfl_xor_sync(0xffffffffu, pd[a][0], off);
            pd[a][1] += __shfl_xor_sync(0xffffffffu, pd[a][1], off);
        }
    }
    if (og == 0) {
        #pragma unroll
        for (int a = 0; a < 4; a++) {
            int gn = nodeBase + ng * 4 + a;
            if (gn < n) {
                *(float2*)&g_asrc[gn * 2] = make_float2(ps[a][0], ps[a][1]);
                *(float2*)&g_adst[gn * 2] = make_float2(pd[a][0], pd[a][1]);
            }
        }
    }
}

// ---------------- K6: per-dst warp — online segment softmax + weighted aggregation ----------------
__global__ __launch_bounds__(256) void k_agg(const float* __restrict__ bias,
                                             float* __restrict__ out, int n) {
    int warp = (blockIdx.x * blockDim.x + threadIdx.x) >> 5;
    int lane = threadIdx.x & 31;
    if (warp >= n) return;
    int node = warp;
    int beg = g_starts[node], end = g_starts[node + 1];

    float ad0 = g_adst[node * 2 + 0], ad1 = g_adst[node * 2 + 1];

    // Pass 1: online max + rescaled sum (lane-parallel over edges)
    float m0 = -INFINITY, m1 = -INFINITY, d0 = 0.f, d1 = 0.f;
    for (int i = beg + lane; i < end; i += 32) {
        int s = g_ssrc[i];
        float2 as = *(const float2*)&g_asrc[s * 2];
        float l0 = lrelu_f(as.x + ad0);
        float l1 = lrelu_f(as.y + ad1);
        float nm0 = fmaxf(m0, l0);
        d0 = d0 * __expf(m0 - nm0) + __expf(l0 - nm0); m0 = nm0;
        float nm1 = fmaxf(m1, l1);
        d1 = d1 * __expf(m1 - nm1) + __expf(l1 - nm1); m1 = nm1;
    }
    #pragma unroll
    for (int o = 16; o; o >>= 1) {
        float om0 = __shfl_xor_sync(0xffffffffu, m0, o);
        float od0 = __shfl_xor_sync(0xffffffffu, d0, o);
        float nm = fmaxf(m0, om0);
        float sa = (m0  > -INFINITY) ? __expf(m0 - nm)  : 0.f;
        float sb = (om0 > -INFINITY) ? __expf(om0 - nm) : 0.f;
        d0 = d0 * sa + od0 * sb; m0 = nm;

        float om1 = __shfl_xor_sync(0xffffffffu, m1, o);
        float od1 = __shfl_xor_sync(0xffffffffu, d1, o);
        float nm1b = fmaxf(m1, om1);
        float sc = (m1  > -INFINITY) ? __expf(m1 - nm1b)  : 0.f;
        float sd = (om1 > -INFINITY) ? __expf(om1 - nm1b) : 0.f;
        d1 = d1 * sc + od1 * sd; m1 = nm1b;
    }
    float inv0 = 1.f / (d0 + 1e-16f);
    float inv1 = 1.f / (d1 + 1e-16f);

    // Pass 2: accumulate alpha * h[src]; lane holds channels c..c+3
    int head = lane >> 4;
    int c = lane * 4;
    float m   = head ? m1   : m0;
    float inv = head ? inv1 : inv0;
    float ad  = head ? ad1  : ad0;

    float4 acc = make_float4(0.f, 0.f, 0.f, 0.f);
    for (int i = beg; i < end; i++) {
        int s = g_ssrc[i];                       // uniform across warp
        float as = g_asrc[s * 2 + head];
        float l = lrelu_f(as + ad);
        float a = __expf(l - m) * inv;
        uint2 raw = *(const uint2*)&g_h[(size_t)s * 128 + c];   // 4 halves
        float2 f01 = __half22float2(*(__half2*)&raw.x);
        float2 f23 = __half22float2(*(__half2*)&raw.y);
        acc.x = fmaf(a, f01.x, acc.x);
        acc.y = fmaf(a, f01.y, acc.y);
        acc.z = fmaf(a, f23.x, acc.z);
        acc.w = fmaf(a, f23.y, acc.w);
    }
    float4 bv = *(const float4*)&bias[c];
    *(float4*)&out[(size_t)node * 128 + c] =
        make_float4(acc.x + bv.x, acc.y + bv.y, acc.z + bv.z, acc.w + bv.w);
}

// ---------------- launch ----------------
extern "C" void kernel_launch(void* const* d_in, const int* in_sizes, int n_in,
                              void* d_out, int out_size) {
    const float* x       = (const float*)d_in[0];
    const int*   ei      = (const int*)d_in[1];    // int32 (JAX downcasts int64)
    const float* W       = (const float*)d_in[2];
    const float* att_src = (const float*)d_in[3];
    const float* att_dst = (const float*)d_in[4];
    const float* bias    = (const float*)d_in[5];
    float*       out     = (float*)d_out;

    int n = in_sizes[0] / 128;   // 100000
    int e = in_sizes[1] / 2;     // 1600000

    k_init<<<(n + 255) / 256, 256>>>(n);
    k_hist<<<(e + 255) / 256, 256>>>(ei, e);
    k_scan<<<1, 1024>>>(n);
    k_scatter<<<(e + n + 255) / 256, 256>>>(ei, e, n);

    k_gemm<<<(n + 31) / 32, 128>>>(x, W, att_src, att_dst, n);

    k_agg<<<(n + 7) / 8, 256>>>(bias, out, n);
}